// round 1
// baseline (speedup 1.0000x reference)
#include <cuda_runtime.h>
#include <cstddef>

// BinaryMaskEdgeSmoothing: fused Laplacian-edge + Gaussian-blur blend + threshold
// on binary masks. Exact integer-combinatorics reduction of the fp32 reference:
//   S9    = 3x3 sum, edges = 9*c - S9, k = |edges|
//   n     = Gauss numerator = S9 + m3 + colsum_center + c   (in 0..16)
//   out   = (n + (k<=5 ? c : 0)) > 8.5        [k>=6 => sigmoid(3k) == 1.0f in fp32]
// Verified equivalent to reference for all 2^9 neighborhoods (see analysis).

#define Wd 1024
#define Hd 1024
#define RPT 16   // output rows per thread

__device__ __forceinline__ void load_row(const float* __restrict__ base, int r, int j,
                                         float v[6]) {
    if ((unsigned)r >= (unsigned)Hd) {
        v[0] = v[1] = v[2] = v[3] = v[4] = v[5] = 0.f;
        return;
    }
    const float* p = base + (size_t)r * Wd + (j << 2);
    float4 cc = __ldg((const float4*)p);
    v[0] = (j > 0) ? __ldg(p - 1) : 0.f;               // left halo (SAME zero pad)
    v[1] = cc.x; v[2] = cc.y; v[3] = cc.z; v[4] = cc.w;
    v[5] = (j < (Wd / 4 - 1)) ? __ldg(p + 4) : 0.f;    // right halo
}

__global__ void __launch_bounds__(256)
mask_smooth_kernel(const float* __restrict__ in, float* __restrict__ out) {
    const int img = blockIdx.y;
    const int r0  = blockIdx.x * RPT;
    const int j   = threadIdx.x;                       // float4 column index 0..255

    const float* base = in  + (size_t)img * Hd * Wd;
    float*       ob   = out + (size_t)img * Hd * Wd;

    float a[6], b[6], c[6];                            // rows r-1, r, r+1 (6-col window)
    load_row(base, r0 - 1, j, a);
    load_row(base, r0,     j, b);

    #pragma unroll
    for (int rr = 0; rr < RPT; ++rr) {
        const int r = r0 + rr;
        load_row(base, r + 1, j, c);

        float cs[6];                                   // vertical column sums
        #pragma unroll
        for (int k = 0; k < 6; ++k) cs[k] = a[k] + b[k] + c[k];

        float res[4];
        #pragma unroll
        for (int i = 0; i < 4; ++i) {
            float S9    = cs[i] + cs[i + 1] + cs[i + 2];
            float m3    = b[i]  + b[i + 1]  + b[i + 2];
            float cv    = b[i + 1];
            float vcen  = cs[i + 1] + cv;              // t_c + 2*m_c + b_c  (m_c == cv)
            float n     = S9 + m3 + vcen;              // Gauss numerator, 0..16
            float edges = fmaf(9.f, cv, -S9);          // Laplacian response, -9..9
            float bonus = (fabsf(edges) < 5.5f) ? cv : 0.f;
            res[i] = (n + bonus > 8.5f) ? 1.f : 0.f;
        }

        float4 o;
        o.x = res[0]; o.y = res[1]; o.z = res[2]; o.w = res[3];
        *(float4*)(ob + (size_t)r * Wd + (j << 2)) = o;

        #pragma unroll
        for (int k = 0; k < 6; ++k) { a[k] = b[k]; b[k] = c[k]; }
    }
}

extern "C" void kernel_launch(void* const* d_in, const int* in_sizes, int n_in,
                              void* d_out, int out_size) {
    const float* mask = (const float*)d_in[0];   // [B*C, H, W] fp32 binary
    float*       outp = (float*)d_out;
    const int nimg = in_sizes[0] / (Hd * Wd);    // 64 for the reference shapes

    dim3 grid(Hd / RPT, nimg);
    mask_smooth_kernel<<<grid, 256>>>(mask, outp);
}